// round 6
// baseline (speedup 1.0000x reference)
#include <cuda_runtime.h>
#include <math.h>

// ---------------------------------------------------------------------------
// Problem constants
// ---------------------------------------------------------------------------
#define T_STEPS 512
#define BATCH   64
#define IN_DIM  1024
#define H_DIM   1024
#define G4      4096            // 4*H
#define KSPLIT  4               // split-K for the per-step GEMM
#define NBLK    128             // persistent-kernel grid (<= 148 SMs, 1 blk/SM)
#define NBAR    (2 * T_STEPS)   // grid barriers used per launch

// Scratch (static __device__ arrays: allocation-free per harness rules)
__device__ float g_xproj[(size_t)T_STEPS * BATCH * G4];   // input projection
__device__ float g_part[KSPLIT * BATCH * G4];             // split-K partials
__device__ float g_c[BATCH * H_DIM];                      // cell state
__device__ int   g_bar[NBAR];                             // grid-barrier slots

// ---------------------------------------------------------------------------
// Software grid barrier (CG-style). Monotonic per-slot counters, zeroed by a
// separate kernel at the start of every launch, so no in-kernel reset race.
// ---------------------------------------------------------------------------
__device__ __forceinline__ void grid_bar(int slot) {
    __syncthreads();
    if (threadIdx.x == 0) {
        __threadfence();                 // release this block's stores
        atomicAdd(&g_bar[slot], 1);
        while (*(volatile int*)&g_bar[slot] < NBLK) __nanosleep(64);
        __threadfence();                 // acquire other blocks' stores
    }
    __syncthreads();
}

__global__ void zero_bar_k() {
    for (int i = threadIdx.x; i < NBAR; i += 256) g_bar[i] = 0;
}

// ---------------------------------------------------------------------------
// Kernel: x_proj = input @ weight_ih^T
// C[M=32768, N=4096] = A[M,1024] * W[N,1024]^T  (both K-contiguous)
// BM=128, BN=128, BK=16, 256 threads, 8x8 register tile.
// ---------------------------------------------------------------------------
__global__ __launch_bounds__(256) void xproj_gemm(const float* __restrict__ A,
                                                  const float* __restrict__ W) {
    __shared__ __align__(16) float As[16][128];
    __shared__ __align__(16) float Bs[16][128];

    const int bn = blockIdx.x;          // N/128 = 32
    const int bm = blockIdx.y;          // M/128 = 256
    const int tid = threadIdx.x;
    const int tm = tid >> 4;            // 0..15 (8 M rows each)
    const int tn = tid & 15;            // 0..15 (8 N cols each)

    float acc[8][8];
#pragma unroll
    for (int i = 0; i < 8; i++)
#pragma unroll
        for (int j = 0; j < 8; j++) acc[i][j] = 0.f;

    const float* Ab = A + (size_t)bm * 128 * IN_DIM;
    const float* Wb = W + (size_t)bn * 128 * IN_DIM;

    for (int kt = 0; kt < IN_DIM; kt += 16) {
        // A tile: 128x16 = 512 float4, 2 per thread (stored k-major)
#pragma unroll
        for (int i = 0; i < 2; i++) {
            int idx = tid * 2 + i;
            int m = idx >> 2, k4 = idx & 3;
            float4 v = *(const float4*)(Ab + (size_t)m * IN_DIM + kt + k4 * 4);
            As[k4 * 4 + 0][m] = v.x;
            As[k4 * 4 + 1][m] = v.y;
            As[k4 * 4 + 2][m] = v.z;
            As[k4 * 4 + 3][m] = v.w;
        }
        // W tile: 128x16 = 512 float4, 2 per thread
#pragma unroll
        for (int i = 0; i < 2; i++) {
            int idx = tid * 2 + i;
            int n = idx >> 2, k4 = idx & 3;
            float4 v = *(const float4*)(Wb + (size_t)n * IN_DIM + kt + k4 * 4);
            Bs[k4 * 4 + 0][n] = v.x;
            Bs[k4 * 4 + 1][n] = v.y;
            Bs[k4 * 4 + 2][n] = v.z;
            Bs[k4 * 4 + 3][n] = v.w;
        }
        __syncthreads();

#pragma unroll
        for (int k = 0; k < 16; k++) {
            const float4 a0 = *(const float4*)&As[k][tm * 8];
            const float4 a1 = *(const float4*)&As[k][tm * 8 + 4];
            const float4 b0 = *(const float4*)&Bs[k][tn * 8];
            const float4 b1 = *(const float4*)&Bs[k][tn * 8 + 4];
            const float a[8] = {a0.x, a0.y, a0.z, a0.w, a1.x, a1.y, a1.z, a1.w};
            const float b[8] = {b0.x, b0.y, b0.z, b0.w, b1.x, b1.y, b1.z, b1.w};
#pragma unroll
            for (int i = 0; i < 8; i++)
#pragma unroll
                for (int j = 0; j < 8; j++)
                    acc[i][j] = fmaf(a[i], b[j], acc[i][j]);
        }
        __syncthreads();
    }

    float* Cb = g_xproj + ((size_t)bm * 128 + tm * 8) * G4 + bn * 128 + tn * 8;
#pragma unroll
    for (int i = 0; i < 8; i++) {
        *(float4*)(Cb + (size_t)i * G4)     = make_float4(acc[i][0], acc[i][1], acc[i][2], acc[i][3]);
        *(float4*)(Cb + (size_t)i * G4 + 4) = make_float4(acc[i][4], acc[i][5], acc[i][6], acc[i][7]);
    }
}

// ---------------------------------------------------------------------------
// Per-step GEMM (device fn, inside persistent kernel):
//   g_part[ks] = h[64,1024] @ Whh[4096,1024]^T  (partial K range per ks)
// Block bid -> (bn = bid&31 : N tile of 128, ks = bid>>5 : K chunk of 256).
// 256 threads = 8 warps; warp w owns M rows [w*8, w*8+8); lane owns 4 N cols.
// A-tile LDS is warp-broadcast; B-tile LDS is conflict-free (contiguous 16B).
// ---------------------------------------------------------------------------
__device__ __forceinline__ void step_gemm_dev(
    const float* __restrict__ h, const float* __restrict__ Whh,
    int bn, int ks, int tid, float (*As)[64], float (*Bs)[128]) {
    const int wm = tid >> 5;            // warp id: 8 M rows each
    const int tn = tid & 31;            // 4 N cols each
    float acc[8][4];
#pragma unroll
    for (int i = 0; i < 8; i++)
#pragma unroll
        for (int j = 0; j < 4; j++) acc[i][j] = 0.f;

    const float* Wb = Whh + (size_t)(bn * 128) * H_DIM;
    const int k0 = ks * (H_DIM / KSPLIT);   // 256-wide K chunk

    for (int kt = 0; kt < H_DIM / KSPLIT; kt += 16) {
        // A (h state): 64x16 = 256 float4, 1 per thread.
        // __ldcg not needed: out[t-1] addresses are touched once -> L1 cold.
        {
            int m = tid >> 2, k4 = tid & 3;
            float4 v = *(const float4*)(h + (size_t)m * H_DIM + k0 + kt + k4 * 4);
            As[k4 * 4 + 0][m] = v.x;
            As[k4 * 4 + 1][m] = v.y;
            As[k4 * 4 + 2][m] = v.z;
            As[k4 * 4 + 3][m] = v.w;
        }
        // B (Whh): 128x16 = 512 float4, 2 per thread (read-only, safe in L1)
#pragma unroll
        for (int i = 0; i < 2; i++) {
            int idx = tid * 2 + i;
            int n = idx >> 2, k4 = idx & 3;
            float4 v = *(const float4*)(Wb + (size_t)n * H_DIM + k0 + kt + k4 * 4);
            Bs[k4 * 4 + 0][n] = v.x;
            Bs[k4 * 4 + 1][n] = v.y;
            Bs[k4 * 4 + 2][n] = v.z;
            Bs[k4 * 4 + 3][n] = v.w;
        }
        __syncthreads();

#pragma unroll
        for (int k = 0; k < 16; k++) {
            const float4 a0 = *(const float4*)&As[k][wm * 8];       // broadcast
            const float4 a1 = *(const float4*)&As[k][wm * 8 + 4];   // broadcast
            const float4 bv = *(const float4*)&Bs[k][tn * 4];       // conflict-free
            const float a[8] = {a0.x, a0.y, a0.z, a0.w, a1.x, a1.y, a1.z, a1.w};
            const float b[4] = {bv.x, bv.y, bv.z, bv.w};
#pragma unroll
            for (int i = 0; i < 8; i++)
#pragma unroll
                for (int j = 0; j < 4; j++)
                    acc[i][j] = fmaf(a[i], b[j], acc[i][j]);
        }
        __syncthreads();
    }

    float* P = g_part + (size_t)ks * BATCH * G4 + (size_t)(wm * 8) * G4 + bn * 128 + tn * 4;
#pragma unroll
    for (int i = 0; i < 8; i++)
        *(float4*)(P + (size_t)i * G4) = make_float4(acc[i][0], acc[i][1], acc[i][2], acc[i][3]);
}

// ---------------------------------------------------------------------------
// Pointwise / LayerNorm (device fn). One block per batch row b (bid < 64).
// 256 threads, each owns 4 of the H=1024 channels (h = tid + j*256).
// g_part is re-read at identical addresses every step across blocks ->
// MUST bypass L1 (__ldcg); L1 is only flushed at launch boundaries.
// ---------------------------------------------------------------------------
__device__ __forceinline__ void blk_stats(float v0, float v1, float v2, float v3,
                                          float* sred, float& mean, float& rstd) {
    float s1 = v0 + v1 + v2 + v3;
    float s2 = v0 * v0 + v1 * v1 + v2 * v2 + v3 * v3;
#pragma unroll
    for (int o = 16; o > 0; o >>= 1) {
        s1 += __shfl_xor_sync(0xffffffffu, s1, o);
        s2 += __shfl_xor_sync(0xffffffffu, s2, o);
    }
    const int w = threadIdx.x >> 5;
    if ((threadIdx.x & 31) == 0) { sred[w] = s1; sred[8 + w] = s2; }
    __syncthreads();
    s1 = sred[0] + sred[1] + sred[2] + sred[3] + sred[4] + sred[5] + sred[6] + sred[7];
    s2 = sred[8] + sred[9] + sred[10] + sred[11] + sred[12] + sred[13] + sred[14] + sred[15];
    __syncthreads();
    mean = s1 * (1.f / 1024.f);
    float var = s2 * (1.f / 1024.f) - mean * mean;
    rstd = rsqrtf(var + 1e-5f);
}

__device__ __forceinline__ float sigm(float x) { return 1.f / (1.f + expf(-x)); }

__device__ __forceinline__ void step_point_dev(
    int t, int b, int tid, const float* __restrict__ cell0,
    const float* __restrict__ wch, const float* __restrict__ bias,
    const float* __restrict__ gf, const float* __restrict__ gi,
    const float* __restrict__ gg, const float* __restrict__ go,
    const float* __restrict__ gcell, const float* __restrict__ bcell,
    float* __restrict__ out, float* sred) {
    const float* xp = g_xproj + ((size_t)t * BATCH + b) * G4;
    const float* p = g_part + (size_t)b * G4;
    const size_t PS = (size_t)BATCH * G4;   // stride between split-K partials

    float vf[4], vi[4], vg[4], vo[4], cold[4];
    int hh[4];
#pragma unroll
    for (int j = 0; j < 4; j++) {
        const int h = tid + j * 256;
        hh[j] = h;
        cold[j] = (t == 0) ? cell0[b * H_DIM + h] : g_c[b * H_DIM + h];
#pragma unroll
        for (int g = 0; g < 4; g++) {
            float s = xp[g * H_DIM + h];
            s += __ldcg(p + 0 * PS + g * H_DIM + h);
            s += __ldcg(p + 1 * PS + g * H_DIM + h);
            s += __ldcg(p + 2 * PS + g * H_DIM + h);
            s += __ldcg(p + 3 * PS + g * H_DIM + h);
            if (g == 0) vf[j] = s + wch[h] * cold[j];
            else if (g == 1) vi[j] = s + wch[H_DIM + h] * cold[j];
            else if (g == 2) vg[j] = s;
            else vo[j] = s;
        }
    }

    float mf, rf, mi, ri, mg, rg;
    blk_stats(vf[0], vf[1], vf[2], vf[3], sred, mf, rf);
    blk_stats(vi[0], vi[1], vi[2], vi[3], sred, mi, ri);
    blk_stats(vg[0], vg[1], vg[2], vg[3], sred, mg, rg);

    float cn[4];
#pragma unroll
    for (int j = 0; j < 4; j++) {
        const int h = hh[j];
        const float fj = sigm((vf[j] - mf) * rf * gf[h] + bias[h]);
        const float ij = sigm((vi[j] - mi) * ri * gi[h] + bias[H_DIM + h]);
        const float gj = tanhf((vg[j] - mg) * rg * gg[h] + bias[2 * H_DIM + h]);
        cn[j] = fj * cold[j] + ij * gj;
    }

    float mc, rc;
    blk_stats(cn[0], cn[1], cn[2], cn[3], sred, mc, rc);

#pragma unroll
    for (int j = 0; j < 4; j++)
        vo[j] += wch[2 * H_DIM + hh[j]] * cn[j];

    float mo, ro;
    blk_stats(vo[0], vo[1], vo[2], vo[3], sred, mo, ro);

#pragma unroll
    for (int j = 0; j < 4; j++) {
        const int h = hh[j];
        const float oj = sigm((vo[j] - mo) * ro * go[h] + bias[3 * H_DIM + h]);
        const float cln = (cn[j] - mc) * rc * gcell[h] + bcell[h];
        const float hn = oj * tanhf(cln);
        out[((size_t)t * BATCH + b) * H_DIM + h] = hn;
        g_c[b * H_DIM + h] = cn[j];
    }
}

// ---------------------------------------------------------------------------
// Persistent recurrence kernel: 512 steps, 2 grid barriers per step.
// Grid = 128 blocks x 256 threads (1 block/SM guaranteed -> no deadlock).
// ---------------------------------------------------------------------------
__global__ __launch_bounds__(256) void recur_persist(
    const float* __restrict__ hidden, const float* __restrict__ cell0,
    const float* __restrict__ Whh, const float* __restrict__ wch,
    const float* __restrict__ bias,
    const float* __restrict__ gf, const float* __restrict__ gi,
    const float* __restrict__ gg, const float* __restrict__ go,
    const float* __restrict__ gcell, const float* __restrict__ bcell,
    float* __restrict__ out) {
    __shared__ __align__(16) float As[16][64];
    __shared__ __align__(16) float Bs[16][128];
    __shared__ float sred[16];

    const int bid = blockIdx.x;
    const int tid = threadIdx.x;
    const int bn = bid & 31;            // N tile (128 wide)
    const int ks = bid >> 5;            // K chunk (256 wide)

    for (int t = 0; t < T_STEPS; t++) {
        const float* h = (t == 0) ? hidden : out + (size_t)(t - 1) * BATCH * H_DIM;
        step_gemm_dev(h, Whh, bn, ks, tid, As, Bs);
        grid_bar(2 * t);
        if (bid < BATCH)
            step_point_dev(t, bid, tid, cell0, wch, bias, gf, gi, gg, go, gcell, bcell, out, sred);
        grid_bar(2 * t + 1);
    }

    // Finalize: h_f = out[T-1], c_f = g_c (appended after out).
    const size_t base = (size_t)T_STEPS * BATCH * H_DIM;
    for (int i = bid * 256 + tid; i < BATCH * H_DIM; i += NBLK * 256) {
        out[base + i] = out[(size_t)(T_STEPS - 1) * BATCH * H_DIM + i];
        out[base + (size_t)BATCH * H_DIM + i] = __ldcg(&g_c[i]);
    }
}

// ---------------------------------------------------------------------------
extern "C" void kernel_launch(void* const* d_in, const int* in_sizes, int n_in,
                              void* d_out, int out_size) {
    const float* input  = (const float*)d_in[0];
    const float* hidden = (const float*)d_in[1];
    const float* cell   = (const float*)d_in[2];
    const float* wih    = (const float*)d_in[3];
    const float* whh    = (const float*)d_in[4];
    const float* wch    = (const float*)d_in[5];
    const float* bias   = (const float*)d_in[6];
    const float* gf     = (const float*)d_in[7];
    const float* gi     = (const float*)d_in[8];
    const float* gg     = (const float*)d_in[9];
    const float* go     = (const float*)d_in[10];
    const float* gcell  = (const float*)d_in[11];
    const float* bcell  = (const float*)d_in[12];
    float* out = (float*)d_out;

    // 3-node graph: barrier reset, x_proj GEMM, persistent recurrence.
    zero_bar_k<<<1, 256>>>();
    xproj_gemm<<<dim3(G4 / 128, (T_STEPS * BATCH) / 128), 256>>>(input, wih);
    recur_persist<<<NBLK, 256>>>(hidden, cell, whh, wch, bias,
                                 gf, gi, gg, go, gcell, bcell, out);
}

// round 8
// speedup vs baseline: 1.3806x; 1.3806x over previous
#include <cuda_runtime.h>
#include <cuda_bf16.h>
#include <stdint.h>
#include <math.h>

// ---------------------------------------------------------------------------
// Problem constants
// ---------------------------------------------------------------------------
#define T_STEPS 512
#define BATCH   64
#define IN_DIM  1024
#define H_DIM   1024
#define G4      4096            // 4*H
#define KSPLIT  4               // split-K for the per-step GEMM
#define NBLK    128             // persistent-kernel grid (<= 148 SMs, 1 blk/SM)
#define NBAR    (2 * T_STEPS)   // grid barriers used per launch
#define LDS_    40              // smem leading dim (bf16 elems); 40*2B=80B rows
                                // -> ldmatrix rows hit 8 distinct banks

// Scratch (static __device__ arrays: allocation-free per harness rules)
__device__ float g_xproj[(size_t)T_STEPS * BATCH * G4];   // input projection
__device__ float g_part[KSPLIT * BATCH * G4];             // split-K partials
__device__ float g_c[BATCH * H_DIM];                      // cell state
__device__ int   g_bar[NBAR];                             // grid-barrier slots

// ---------------------------------------------------------------------------
// Grid barrier (CG-style). Monotonic per-slot counters, zeroed per launch.
// ---------------------------------------------------------------------------
__device__ __forceinline__ void grid_bar(int slot) {
    __syncthreads();
    if (threadIdx.x == 0) {
        __threadfence();
        atomicAdd(&g_bar[slot], 1);
        while (*(volatile int*)&g_bar[slot] < NBLK) __nanosleep(64);
        __threadfence();
    }
    __syncthreads();
}

__global__ void zero_bar_k() {
    for (int i = threadIdx.x; i < NBAR; i += 256) g_bar[i] = 0;
}

// ---------------------------------------------------------------------------
// Tensor-core helpers: mma.sync m16n8k16 bf16 + ldmatrix
// ---------------------------------------------------------------------------
__device__ __forceinline__ uint32_t smem_u32(const void* p) {
    return (uint32_t)__cvta_generic_to_shared(p);
}

__device__ __forceinline__ void ldm_x4(uint32_t r[4], uint32_t a) {
    asm volatile("ldmatrix.sync.aligned.m8n8.x4.shared.b16 {%0,%1,%2,%3}, [%4];\n"
                 : "=r"(r[0]), "=r"(r[1]), "=r"(r[2]), "=r"(r[3]) : "r"(a));
}

__device__ __forceinline__ void mma_bf(float d[4], const uint32_t a[4], const uint32_t b[2]) {
    asm volatile(
        "mma.sync.aligned.m16n8k16.row.col.f32.bf16.bf16.f32 "
        "{%0,%1,%2,%3}, {%4,%5,%6,%7}, {%8,%9}, {%0,%1,%2,%3};\n"
        : "+f"(d[0]), "+f"(d[1]), "+f"(d[2]), "+f"(d[3])
        : "r"(a[0]), "r"(a[1]), "r"(a[2]), "r"(a[3]), "r"(b[0]), "r"(b[1]));
}

// A-tile (row-major [m][k], ld=LDS_) ldmatrix.x4 address for (m0..m0+15, k0..k0+15)
__device__ __forceinline__ uint32_t a_addr(uint32_t base, int m0, int k0, int lane) {
    int r = m0 + (lane & 7) + ((lane >> 3) & 1) * 8;
    int c = k0 + (lane >> 4) * 8;
    return base + (uint32_t)(r * LDS_ + c) * 2u;
}
// B-tile (row-major [n][k], ld=LDS_) ldmatrix.x4 address covering 16 n, 16 k:
// matrices: (n0,k0)(n0,k8)(n8,k0)(n8,k8) -> {b0,b1} of nfrag0, {b0,b1} of nfrag1
__device__ __forceinline__ uint32_t b_addr(uint32_t base, int n0, int k0, int lane) {
    int r = n0 + (lane & 7) + ((lane >> 4) & 1) * 8;
    int c = k0 + ((lane >> 3) & 1) * 8;
    return base + (uint32_t)(r * LDS_ + c) * 2u;
}

// Split fp32x4 -> bf16 hi/lo x4, store to smem (4B-aligned positions)
__device__ __forceinline__ void split_store4(float4 v, __nv_bfloat16* hi, __nv_bfloat16* lo) {
    __nv_bfloat16 h0 = __float2bfloat16(v.x), h1 = __float2bfloat16(v.y);
    __nv_bfloat16 h2 = __float2bfloat16(v.z), h3 = __float2bfloat16(v.w);
    __nv_bfloat16 l0 = __float2bfloat16(v.x - __bfloat162float(h0));
    __nv_bfloat16 l1 = __float2bfloat16(v.y - __bfloat162float(h1));
    __nv_bfloat16 l2 = __float2bfloat16(v.z - __bfloat162float(h2));
    __nv_bfloat16 l3 = __float2bfloat16(v.w - __bfloat162float(h3));
    uint32_t* hp = (uint32_t*)hi;
    uint32_t* lp = (uint32_t*)lo;
    __nv_bfloat162 t0 = __halves2bfloat162(h0, h1);
    __nv_bfloat162 t1 = __halves2bfloat162(h2, h3);
    __nv_bfloat162 t2 = __halves2bfloat162(l0, l1);
    __nv_bfloat162 t3 = __halves2bfloat162(l2, l3);
    hp[0] = *(uint32_t*)&t0;
    hp[1] = *(uint32_t*)&t1;
    lp[0] = *(uint32_t*)&t2;
    lp[1] = *(uint32_t*)&t3;
}

// ---------------------------------------------------------------------------
// Kernel: x_proj = input @ weight_ih^T   (split-bf16 tensor cores)
// C[32768, 4096], BM=128, BN=128, BK=32, 256 thr, warps 4Mx2N (32x64 tiles)
// ---------------------------------------------------------------------------
__global__ __launch_bounds__(256) void xproj_gemm(const float* __restrict__ A,
                                                  const float* __restrict__ W) {
    __shared__ __align__(16) __nv_bfloat16 Ah[128 * LDS_], Al[128 * LDS_];
    __shared__ __align__(16) __nv_bfloat16 Bh[128 * LDS_], Bl[128 * LDS_];

    const int bn = blockIdx.x, bm = blockIdx.y, tid = threadIdx.x;
    const int wid = tid >> 5, lane = tid & 31;
    const int wm = (wid >> 1) * 32;     // warp M origin (4 warps)
    const int wn = (wid & 1) * 64;      // warp N origin (2 warps)

    float acc[2][8][4];
#pragma unroll
    for (int i = 0; i < 2; i++)
#pragma unroll
        for (int j = 0; j < 8; j++)
#pragma unroll
            for (int k = 0; k < 4; k++) acc[i][j][k] = 0.f;

    const float* Ab = A + (size_t)bm * 128 * IN_DIM;
    const float* Wb = W + (size_t)bn * 128 * IN_DIM;
    const int lr = tid >> 3;            // 0..31
    const int lc = (tid & 7) * 4;       // 0..28

    const uint32_t sAh = smem_u32(Ah), sAl = smem_u32(Al);
    const uint32_t sBh = smem_u32(Bh), sBl = smem_u32(Bl);

    // software-pipelined: prefetch tile kt+32 into regs during mma of tile kt
    float4 av[4], wv[4];
#pragma unroll
    for (int i = 0; i < 4; i++) {
        av[i] = *(const float4*)(Ab + (size_t)(lr + i * 32) * IN_DIM + lc);
        wv[i] = *(const float4*)(Wb + (size_t)(lr + i * 32) * IN_DIM + lc);
    }

    for (int kt = 0; kt < IN_DIM; kt += 32) {
#pragma unroll
        for (int i = 0; i < 4; i++) {
            int r = lr + i * 32;
            split_store4(av[i], &Ah[r * LDS_ + lc], &Al[r * LDS_ + lc]);
            split_store4(wv[i], &Bh[r * LDS_ + lc], &Bl[r * LDS_ + lc]);
        }
        __syncthreads();
        if (kt + 32 < IN_DIM) {
#pragma unroll
            for (int i = 0; i < 4; i++) {
                av[i] = *(const float4*)(Ab + (size_t)(lr + i * 32) * IN_DIM + kt + 32 + lc);
                wv[i] = *(const float4*)(Wb + (size_t)(lr + i * 32) * IN_DIM + kt + 32 + lc);
            }
        }
#pragma unroll
        for (int kk = 0; kk < 32; kk += 16) {
            uint32_t ah[2][4], al[2][4];
#pragma unroll
            for (int mf = 0; mf < 2; mf++) {
                ldm_x4(ah[mf], a_addr(sAh, wm + mf * 16, kk, lane));
                ldm_x4(al[mf], a_addr(sAl, wm + mf * 16, kk, lane));
            }
            uint32_t bh[8][2], bl[8][2];
#pragma unroll
            for (int np = 0; np < 4; np++) {
                uint32_t t[4];
                ldm_x4(t, b_addr(sBh, wn + np * 16, kk, lane));
                bh[np * 2][0] = t[0]; bh[np * 2][1] = t[1];
                bh[np * 2 + 1][0] = t[2]; bh[np * 2 + 1][1] = t[3];
                ldm_x4(t, b_addr(sBl, wn + np * 16, kk, lane));
                bl[np * 2][0] = t[0]; bl[np * 2][1] = t[1];
                bl[np * 2 + 1][0] = t[2]; bl[np * 2 + 1][1] = t[3];
            }
#pragma unroll
            for (int mf = 0; mf < 2; mf++)
#pragma unroll
                for (int nf = 0; nf < 8; nf++) {
                    mma_bf(acc[mf][nf], ah[mf], bh[nf]);
                    mma_bf(acc[mf][nf], ah[mf], bl[nf]);
                    mma_bf(acc[mf][nf], al[mf], bh[nf]);
                }
        }
        __syncthreads();
    }

    // epilogue: c0,c1 -> (m, 2q..2q+1); c2,c3 -> (m+8, ...)
    const int qr = lane >> 2, qc = (lane & 3) * 2;
    float* Cb = g_xproj + ((size_t)(bm * 128 + wm)) * G4 + bn * 128 + wn;
#pragma unroll
    for (int mf = 0; mf < 2; mf++)
#pragma unroll
        for (int nf = 0; nf < 8; nf++) {
            float* p = Cb + (size_t)(mf * 16 + qr) * G4 + nf * 8 + qc;
            *(float2*)p = make_float2(acc[mf][nf][0], acc[mf][nf][1]);
            *(float2*)(p + (size_t)8 * G4) = make_float2(acc[mf][nf][2], acc[mf][nf][3]);
        }
}

// ---------------------------------------------------------------------------
// Per-step GEMM (device fn): g_part[ks] = h[64,1024] @ Whh^T (K chunk per ks)
// M=64, BN=128, BK=32; warps 2Mx4N (32x32 tiles). Split-bf16, 3-term.
// ---------------------------------------------------------------------------
__device__ __forceinline__ void step_gemm_dev(
    const float* __restrict__ h, const float* __restrict__ Whh,
    int bn, int ks, int tid,
    __nv_bfloat16* Ah, __nv_bfloat16* Al, __nv_bfloat16* Bh, __nv_bfloat16* Bl) {
    const int wid = tid >> 5, lane = tid & 31;
    const int wm = (wid >> 2) * 32;     // 2 warps in M
    const int wn = (wid & 3) * 32;      // 4 warps in N

    float acc[2][4][4];
#pragma unroll
    for (int i = 0; i < 2; i++)
#pragma unroll
        for (int j = 0; j < 4; j++)
#pragma unroll
            for (int k = 0; k < 4; k++) acc[i][j][k] = 0.f;

    const float* Wb = Whh + (size_t)(bn * 128) * H_DIM;
    const int k0 = ks * (H_DIM / KSPLIT);   // 256-wide K chunk
    const int lr = tid >> 3;            // 0..31
    const int lc = (tid & 7) * 4;

    const uint32_t sAh = smem_u32(Ah), sAl = smem_u32(Al);
    const uint32_t sBh = smem_u32(Bh), sBl = smem_u32(Bl);

    float4 av[2], wv[4];
#pragma unroll
    for (int i = 0; i < 2; i++)
        av[i] = *(const float4*)(h + (size_t)(lr + i * 32) * H_DIM + k0 + lc);
#pragma unroll
    for (int i = 0; i < 4; i++)
        wv[i] = *(const float4*)(Wb + (size_t)(lr + i * 32) * H_DIM + k0 + lc);

    for (int kt = 0; kt < H_DIM / KSPLIT; kt += 32) {
#pragma unroll
        for (int i = 0; i < 2; i++) {
            int r = lr + i * 32;
            split_store4(av[i], &Ah[r * LDS_ + lc], &Al[r * LDS_ + lc]);
        }
#pragma unroll
        for (int i = 0; i < 4; i++) {
            int r = lr + i * 32;
            split_store4(wv[i], &Bh[r * LDS_ + lc], &Bl[r * LDS_ + lc]);
        }
        __syncthreads();
        if (kt + 32 < H_DIM / KSPLIT) {
#pragma unroll
            for (int i = 0; i < 2; i++)
                av[i] = *(const float4*)(h + (size_t)(lr + i * 32) * H_DIM + k0 + kt + 32 + lc);
#pragma unroll
            for (int i = 0; i < 4; i++)
                wv[i] = *(const float4*)(Wb + (size_t)(lr + i * 32) * H_DIM + k0 + kt + 32 + lc);
        }
#pragma unroll
        for (int kk = 0; kk < 32; kk += 16) {
            uint32_t ah[2][4], al[2][4];
#pragma unroll
            for (int mf = 0; mf < 2; mf++) {
                ldm_x4(ah[mf], a_addr(sAh, wm + mf * 16, kk, lane));
                ldm_x4(al[mf], a_addr(sAl, wm + mf * 16, kk, lane));
            }
            uint32_t bh[4][2], bl[4][2];
#pragma unroll
            for (int np = 0; np < 2; np++) {
                uint32_t t[4];
                ldm_x4(t, b_addr(sBh, wn + np * 16, kk, lane));
                bh[np * 2][0] = t[0]; bh[np * 2][1] = t[1];
                bh[np * 2 + 1][0] = t[2]; bh[np * 2 + 1][1] = t[3];
                ldm_x4(t, b_addr(sBl, wn + np * 16, kk, lane));
                bl[np * 2][0] = t[0]; bl[np * 2][1] = t[1];
                bl[np * 2 + 1][0] = t[2]; bl[np * 2 + 1][1] = t[3];
            }
#pragma unroll
            for (int mf = 0; mf < 2; mf++)
#pragma unroll
                for (int nf = 0; nf < 4; nf++) {
                    mma_bf(acc[mf][nf], ah[mf], bh[nf]);
                    mma_bf(acc[mf][nf], ah[mf], bl[nf]);
                    mma_bf(acc[mf][nf], al[mf], bh[nf]);
                }
        }
        __syncthreads();
    }

    const int qr = lane >> 2, qc = (lane & 3) * 2;
    float* P = g_part + (size_t)ks * BATCH * G4 + (size_t)wm * G4 + bn * 128 + wn;
#pragma unroll
    for (int mf = 0; mf < 2; mf++)
#pragma unroll
        for (int nf = 0; nf < 4; nf++) {
            float* p = P + (size_t)(mf * 16 + qr) * G4 + nf * 8 + qc;
            *(float2*)p = make_float2(acc[mf][nf][0], acc[mf][nf][1]);
            *(float2*)(p + (size_t)8 * G4) = make_float2(acc[mf][nf][2], acc[mf][nf][3]);
        }
}

// ---------------------------------------------------------------------------
// Pointwise / LayerNorm (device fn). One block per batch row b (bid < 64).
// g_part re-read at identical addresses cross-block every step -> __ldcg.
// ---------------------------------------------------------------------------
__device__ __forceinline__ void blk_stats(float v0, float v1, float v2, float v3,
                                          float* sred, float& mean, float& rstd) {
    float s1 = v0 + v1 + v2 + v3;
    float s2 = v0 * v0 + v1 * v1 + v2 * v2 + v3 * v3;
#pragma unroll
    for (int o = 16; o > 0; o >>= 1) {
        s1 += __shfl_xor_sync(0xffffffffu, s1, o);
        s2 += __shfl_xor_sync(0xffffffffu, s2, o);
    }
    const int w = threadIdx.x >> 5;
    if ((threadIdx.x & 31) == 0) { sred[w] = s1; sred[8 + w] = s2; }
    __syncthreads();
    s1 = sred[0] + sred[1] + sred[2] + sred[3] + sred[4] + sred[5] + sred[6] + sred[7];
    s2 = sred[8] + sred[9] + sred[10] + sred[11] + sred[12] + sred[13] + sred[14] + sred[15];
    __syncthreads();
    mean = s1 * (1.f / 1024.f);
    float var = s2 * (1.f / 1024.f) - mean * mean;
    rstd = rsqrtf(var + 1e-5f);
}

__device__ __forceinline__ float sigm(float x) { return 1.f / (1.f + expf(-x)); }

__device__ __forceinline__ void step_point_dev(
    int t, int b, int tid, const float* __restrict__ cell0,
    const float* __restrict__ wch, const float* __restrict__ bias,
    const float* __restrict__ gf, const float* __restrict__ gi,
    const float* __restrict__ gg, const float* __restrict__ go,
    const float* __restrict__ gcell, const float* __restrict__ bcell,
    float* __restrict__ out, float* sred) {
    const float* xp = g_xproj + ((size_t)t * BATCH + b) * G4;
    const float* p = g_part + (size_t)b * G4;
    const size_t PS = (size_t)BATCH * G4;

    float vf[4], vi[4], vg[4], vo[4], cold[4];
    int hh[4];
#pragma unroll
    for (int j = 0; j < 4; j++) {
        const int h = tid + j * 256;
        hh[j] = h;
        cold[j] = (t == 0) ? cell0[b * H_DIM + h] : g_c[b * H_DIM + h];
#pragma unroll
        for (int g = 0; g < 4; g++) {
            float s = xp[g * H_DIM + h];
            s += __ldcg(p + 0 * PS + g * H_DIM + h);
            s += __ldcg(p + 1 * PS + g * H_DIM + h);
            s += __ldcg(p + 2 * PS + g * H_DIM + h);
            s += __ldcg(p + 3 * PS + g * H_DIM + h);
            if (g == 0) vf[j] = s + wch[h] * cold[j];
            else if (g == 1) vi[j] = s + wch[H_DIM + h] * cold[j];
            else if (g == 2) vg[j] = s;
            else vo[j] = s;
        }
    }

    float mf, rf, mi, ri, mg, rg;
    blk_stats(vf[0], vf[1], vf[2], vf[3], sred, mf, rf);
    blk_stats(vi[0], vi[1], vi[2], vi[3], sred, mi, ri);
    blk_stats(vg[0], vg[1], vg[2], vg[3], sred, mg, rg);

    float cn[4];
#pragma unroll
    for (int j = 0; j < 4; j++) {
        const int h = hh[j];
        const float fj = sigm((vf[j] - mf) * rf * gf[h] + bias[h]);
        const float ij = sigm((vi[j] - mi) * ri * gi[h] + bias[H_DIM + h]);
        const float gj = tanhf((vg[j] - mg) * rg * gg[h] + bias[2 * H_DIM + h]);
        cn[j] = fj * cold[j] + ij * gj;
    }

    float mc, rc;
    blk_stats(cn[0], cn[1], cn[2], cn[3], sred, mc, rc);

#pragma unroll
    for (int j = 0; j < 4; j++)
        vo[j] += wch[2 * H_DIM + hh[j]] * cn[j];

    float mo, ro;
    blk_stats(vo[0], vo[1], vo[2], vo[3], sred, mo, ro);

#pragma unroll
    for (int j = 0; j < 4; j++) {
        const int h = hh[j];
        const float oj = sigm((vo[j] - mo) * ro * go[h] + bias[3 * H_DIM + h]);
        const float cln = (cn[j] - mc) * rc * gcell[h] + bcell[h];
        const float hn = oj * tanhf(cln);
        out[((size_t)t * BATCH + b) * H_DIM + h] = hn;
        g_c[b * H_DIM + h] = cn[j];
    }
}

// ---------------------------------------------------------------------------
// Persistent recurrence kernel: 512 steps, 2 grid barriers per step.
// Grid = 128 blocks x 256 threads (1 block/SM -> no deadlock).
// ---------------------------------------------------------------------------
__global__ __launch_bounds__(256) void recur_persist(
    const float* __restrict__ hidden, const float* __restrict__ cell0,
    const float* __restrict__ Whh, const float* __restrict__ wch,
    const float* __restrict__ bias,
    const float* __restrict__ gf, const float* __restrict__ gi,
    const float* __restrict__ gg, const float* __restrict__ go,
    const float* __restrict__ gcell, const float* __restrict__ bcell,
    float* __restrict__ out) {
    __shared__ __align__(16) __nv_bfloat16 Ah[64 * LDS_], Al[64 * LDS_];
    __shared__ __align__(16) __nv_bfloat16 Bh[128 * LDS_], Bl[128 * LDS_];
    __shared__ float sred[16];

    const int bid = blockIdx.x;
    const int tid = threadIdx.x;
    const int bn = bid & 31;            // N tile (128 wide)
    const int ks = bid >> 5;            // K chunk (256 wide)

    for (int t = 0; t < T_STEPS; t++) {
        const float* h = (t == 0) ? hidden : out + (size_t)(t - 1) * BATCH * H_DIM;
        step_gemm_dev(h, Whh, bn, ks, tid, Ah, Al, Bh, Bl);
        grid_bar(2 * t);
        if (bid < BATCH)
            step_point_dev(t, bid, tid, cell0, wch, bias, gf, gi, gg, go, gcell, bcell, out, sred);
        grid_bar(2 * t + 1);
    }

    // Finalize: h_f = out[T-1], c_f = g_c (appended after out).
    const size_t base = (size_t)T_STEPS * BATCH * H_DIM;
    for (int i = bid * 256 + tid; i < BATCH * H_DIM; i += NBLK * 256) {
        out[base + i] = out[(size_t)(T_STEPS - 1) * BATCH * H_DIM + i];
        out[base + (size_t)BATCH * H_DIM + i] = __ldcg(&g_c[i]);
    }
}

// ---------------------------------------------------------------------------
extern "C" void kernel_launch(void* const* d_in, const int* in_sizes, int n_in,
                              void* d_out, int out_size) {
    const float* input  = (const float*)d_in[0];
    const float* hidden = (const float*)d_in[1];
    const float* cell   = (const float*)d_in[2];
    const float* wih    = (const float*)d_in[3];
    const float* whh    = (const float*)d_in[4];
    const float* wch    = (const float*)d_in[5];
    const float* bias   = (const float*)d_in[6];
    const float* gf     = (const float*)d_in[7];
    const float* gi     = (const float*)d_in[8];
    const float* gg     = (const float*)d_in[9];
    const float* go     = (const float*)d_in[10];
    const float* gcell  = (const float*)d_in[11];
    const float* bcell  = (const float*)d_in[12];
    float* out = (float*)d_out;

    // 3-node graph: barrier reset, x_proj GEMM, persistent recurrence.
    zero_bar_k<<<1, 256>>>();
    xproj_gemm<<<dim3(G4 / 128, (T_STEPS * BATCH) / 128), 256>>>(input, wih);
    recur_persist<<<NBLK, 256>>>(hidden, cell, whh, wch, bias,
                                 gf, gi, gg, go, gcell, bcell, out);
}

// round 10
// speedup vs baseline: 2.3881x; 1.7298x over previous
#include <cuda_runtime.h>
#include <cuda_bf16.h>
#include <stdint.h>
#include <math.h>

// ---------------------------------------------------------------------------
// Problem constants
// ---------------------------------------------------------------------------
#define T_STEPS 512
#define BATCH   64
#define IN_DIM  1024
#define H_DIM   1024
#define G4      4096            // 4*H
#define KSPLIT  4               // split-K for the per-step GEMM
#define NBLK    128             // persistent-kernel grid (1 blk/SM, <=148 SMs)
#define NBAR    (2 * T_STEPS)   // grid barriers used per launch
#define BAR_NC  8               // counters per barrier slot
#define BAR_ST  512             // ints per slot (counters at 64-int = 256B stride)
#define LDS_    40              // xproj smem leading dim (bf16)
#define LDW_    264             // resident-W / A smem leading dim (bf16); 528B rows
                                // -> ldmatrix rows step 4 banks: conflict-free

// Scratch (static __device__ arrays: allocation-free per harness rules)
__device__ float g_xproj[(size_t)T_STEPS * BATCH * G4];   // input projection
__device__ float g_part[KSPLIT * BATCH * G4];             // split-K partials
__device__ float g_c[BATCH * H_DIM];                      // cell state
__device__ int   g_bar[NBAR * BAR_ST];                    // grid-barrier slots

// ---------------------------------------------------------------------------
// Grid barrier: 8 spread counters per slot (parallel LTS atomics), monotonic,
// zeroed per launch by zero_bar_k.
// ---------------------------------------------------------------------------
__device__ __forceinline__ void grid_bar(int slot) {
    __syncthreads();
    if (threadIdx.x == 0) {
        __threadfence();
        atomicAdd(&g_bar[slot * BAR_ST + (blockIdx.x & (BAR_NC - 1)) * 64], 1);
        int s;
        do {
            s = 0;
#pragma unroll
            for (int i = 0; i < BAR_NC; i++)
                s += ((volatile int*)g_bar)[slot * BAR_ST + i * 64];
            if (s < NBLK) __nanosleep(32);
        } while (s < NBLK);
        __threadfence();
    }
    __syncthreads();
}

__global__ void zero_bar_k() {
    const int n = NBAR * BAR_ST;
    for (int i = blockIdx.x * 256 + threadIdx.x; i < n; i += 64 * 256) g_bar[i] = 0;
}

// ---------------------------------------------------------------------------
// Tensor-core helpers: mma.sync m16n8k16 bf16 + ldmatrix
// ---------------------------------------------------------------------------
__device__ __forceinline__ uint32_t smem_u32(const void* p) {
    return (uint32_t)__cvta_generic_to_shared(p);
}

__device__ __forceinline__ void ldm_x4(uint32_t r[4], uint32_t a) {
    asm volatile("ldmatrix.sync.aligned.m8n8.x4.shared.b16 {%0,%1,%2,%3}, [%4];\n"
                 : "=r"(r[0]), "=r"(r[1]), "=r"(r[2]), "=r"(r[3]) : "r"(a));
}

__device__ __forceinline__ void mma_bf(float d[4], const uint32_t a[4], const uint32_t b[2]) {
    asm volatile(
        "mma.sync.aligned.m16n8k16.row.col.f32.bf16.bf16.f32 "
        "{%0,%1,%2,%3}, {%4,%5,%6,%7}, {%8,%9}, {%0,%1,%2,%3};\n"
        : "+f"(d[0]), "+f"(d[1]), "+f"(d[2]), "+f"(d[3])
        : "r"(a[0]), "r"(a[1]), "r"(a[2]), "r"(a[3]), "r"(b[0]), "r"(b[1]));
}

// A-tile (row-major [m][k], leading dim LD) ldmatrix.x4 address
template <int LD>
__device__ __forceinline__ uint32_t a_addrT(uint32_t base, int m0, int k0, int lane) {
    int r = m0 + (lane & 7) + ((lane >> 3) & 1) * 8;
    int c = k0 + (lane >> 4) * 8;
    return base + (uint32_t)(r * LD + c) * 2u;
}
// B-tile (row-major [n][k], leading dim LD) ldmatrix.x4 address (16n x 16k)
template <int LD>
__device__ __forceinline__ uint32_t b_addrT(uint32_t base, int n0, int k0, int lane) {
    int r = n0 + (lane & 7) + ((lane >> 4) & 1) * 8;
    int c = k0 + ((lane >> 3) & 1) * 8;
    return base + (uint32_t)(r * LD + c) * 2u;
}

// Split fp32x4 -> bf16 hi/lo x4, store to smem (4B-aligned positions)
__device__ __forceinline__ void split_store4(float4 v, __nv_bfloat16* hi, __nv_bfloat16* lo) {
    __nv_bfloat16 h0 = __float2bfloat16(v.x), h1 = __float2bfloat16(v.y);
    __nv_bfloat16 h2 = __float2bfloat16(v.z), h3 = __float2bfloat16(v.w);
    __nv_bfloat16 l0 = __float2bfloat16(v.x - __bfloat162float(h0));
    __nv_bfloat16 l1 = __float2bfloat16(v.y - __bfloat162float(h1));
    __nv_bfloat16 l2 = __float2bfloat16(v.z - __bfloat162float(h2));
    __nv_bfloat16 l3 = __float2bfloat16(v.w - __bfloat162float(h3));
    uint32_t* hp = (uint32_t*)hi;
    uint32_t* lp = (uint32_t*)lo;
    __nv_bfloat162 t0 = __halves2bfloat162(h0, h1);
    __nv_bfloat162 t1 = __halves2bfloat162(h2, h3);
    __nv_bfloat162 t2 = __halves2bfloat162(l0, l1);
    __nv_bfloat162 t3 = __halves2bfloat162(l2, l3);
    hp[0] = *(uint32_t*)&t0;
    hp[1] = *(uint32_t*)&t1;
    lp[0] = *(uint32_t*)&t2;
    lp[1] = *(uint32_t*)&t3;
}

// ---------------------------------------------------------------------------
// Kernel: x_proj = input @ weight_ih^T   (split-bf16 tensor cores) — unchanged
// C[32768, 4096], BM=128, BN=128, BK=32, 256 thr, warps 4Mx2N (32x64 tiles)
// ---------------------------------------------------------------------------
__global__ __launch_bounds__(256) void xproj_gemm(const float* __restrict__ A,
                                                  const float* __restrict__ W) {
    __shared__ __align__(16) __nv_bfloat16 Ah[128 * LDS_], Al[128 * LDS_];
    __shared__ __align__(16) __nv_bfloat16 Bh[128 * LDS_], Bl[128 * LDS_];

    const int bn = blockIdx.x, bm = blockIdx.y, tid = threadIdx.x;
    const int wid = tid >> 5, lane = tid & 31;
    const int wm = (wid >> 1) * 32;
    const int wn = (wid & 1) * 64;

    float acc[2][8][4];
#pragma unroll
    for (int i = 0; i < 2; i++)
#pragma unroll
        for (int j = 0; j < 8; j++)
#pragma unroll
            for (int k = 0; k < 4; k++) acc[i][j][k] = 0.f;

    const float* Ab = A + (size_t)bm * 128 * IN_DIM;
    const float* Wb = W + (size_t)bn * 128 * IN_DIM;
    const int lr = tid >> 3;
    const int lc = (tid & 7) * 4;

    const uint32_t sAh = smem_u32(Ah), sAl = smem_u32(Al);
    const uint32_t sBh = smem_u32(Bh), sBl = smem_u32(Bl);

    float4 av[4], wv[4];
#pragma unroll
    for (int i = 0; i < 4; i++) {
        av[i] = *(const float4*)(Ab + (size_t)(lr + i * 32) * IN_DIM + lc);
        wv[i] = *(const float4*)(Wb + (size_t)(lr + i * 32) * IN_DIM + lc);
    }

    for (int kt = 0; kt < IN_DIM; kt += 32) {
#pragma unroll
        for (int i = 0; i < 4; i++) {
            int r = lr + i * 32;
            split_store4(av[i], &Ah[r * LDS_ + lc], &Al[r * LDS_ + lc]);
            split_store4(wv[i], &Bh[r * LDS_ + lc], &Bl[r * LDS_ + lc]);
        }
        __syncthreads();
        if (kt + 32 < IN_DIM) {
#pragma unroll
            for (int i = 0; i < 4; i++) {
                av[i] = *(const float4*)(Ab + (size_t)(lr + i * 32) * IN_DIM + kt + 32 + lc);
                wv[i] = *(const float4*)(Wb + (size_t)(lr + i * 32) * IN_DIM + kt + 32 + lc);
            }
        }
#pragma unroll
        for (int kk = 0; kk < 32; kk += 16) {
            uint32_t ah[2][4], al[2][4];
#pragma unroll
            for (int mf = 0; mf < 2; mf++) {
                ldm_x4(ah[mf], a_addrT<LDS_>(sAh, wm + mf * 16, kk, lane));
                ldm_x4(al[mf], a_addrT<LDS_>(sAl, wm + mf * 16, kk, lane));
            }
            uint32_t bh[8][2], bl[8][2];
#pragma unroll
            for (int np = 0; np < 4; np++) {
                uint32_t t[4];
                ldm_x4(t, b_addrT<LDS_>(sBh, wn + np * 16, kk, lane));
                bh[np * 2][0] = t[0]; bh[np * 2][1] = t[1];
                bh[np * 2 + 1][0] = t[2]; bh[np * 2 + 1][1] = t[3];
                ldm_x4(t, b_addrT<LDS_>(sBl, wn + np * 16, kk, lane));
                bl[np * 2][0] = t[0]; bl[np * 2][1] = t[1];
                bl[np * 2 + 1][0] = t[2]; bl[np * 2 + 1][1] = t[3];
            }
#pragma unroll
            for (int mf = 0; mf < 2; mf++)
#pragma unroll
                for (int nf = 0; nf < 8; nf++) {
                    mma_bf(acc[mf][nf], ah[mf], bh[nf]);
                    mma_bf(acc[mf][nf], ah[mf], bl[nf]);
                    mma_bf(acc[mf][nf], al[mf], bh[nf]);
                }
        }
        __syncthreads();
    }

    const int qr = lane >> 2, qc = (lane & 3) * 2;
    float* Cb = g_xproj + ((size_t)(bm * 128 + wm)) * G4 + bn * 128 + wn;
#pragma unroll
    for (int mf = 0; mf < 2; mf++)
#pragma unroll
        for (int nf = 0; nf < 8; nf++) {
            float* p = Cb + (size_t)(mf * 16 + qr) * G4 + nf * 8 + qc;
            *(float2*)p = make_float2(acc[mf][nf][0], acc[mf][nf][1]);
            *(float2*)(p + (size_t)8 * G4) = make_float2(acc[mf][nf][2], acc[mf][nf][3]);
        }
}

// ---------------------------------------------------------------------------
// Per-step GEMM with RESIDENT split-bf16 W in smem.
// g_part[ks] = h[64,1024] @ Whh^T (K chunk 256 per ks, N tile 128 per bn)
// Per step: bulk A load+split (16 float4/thread), ONE sync, pure mma loop.
// ---------------------------------------------------------------------------
__device__ __forceinline__ void step_gemm_res(
    const float* __restrict__ h, int bn, int ks, int tid,
    __nv_bfloat16* Ah, __nv_bfloat16* Al,
    const __nv_bfloat16* Wh, const __nv_bfloat16* Wl) {
    const int k0 = ks * 256;

    // Bulk A tile: 64 rows x 256 K fp32 -> split hi/lo into smem
#pragma unroll
    for (int i = 0; i < 16; i++) {
        int idx = tid + i * 256;            // 0..4095 float4 slots
        int n = idx >> 6, c4 = (idx & 63) * 4;
        float4 v = *(const float4*)(h + (size_t)n * H_DIM + k0 + c4);
        split_store4(v, &Ah[n * LDW_ + c4], &Al[n * LDW_ + c4]);
    }
    __syncthreads();

    const int wid = tid >> 5, lane = tid & 31;
    const int wm = (wid >> 2) * 32;     // 2 warps in M (32 rows each)
    const int wn = (wid & 3) * 32;      // 4 warps in N (32 cols each)

    float acc[2][4][4];
#pragma unroll
    for (int i = 0; i < 2; i++)
#pragma unroll
        for (int j = 0; j < 4; j++)
#pragma unroll
            for (int k = 0; k < 4; k++) acc[i][j][k] = 0.f;

    const uint32_t sAh = smem_u32(Ah), sAl = smem_u32(Al);
    const uint32_t sWh = smem_u32(Wh), sWl = smem_u32(Wl);

#pragma unroll 4
    for (int kk = 0; kk < 256; kk += 16) {
        uint32_t ah[2][4], al[2][4];
#pragma unroll
        for (int mf = 0; mf < 2; mf++) {
            ldm_x4(ah[mf], a_addrT<LDW_>(sAh, wm + mf * 16, kk, lane));
            ldm_x4(al[mf], a_addrT<LDW_>(sAl, wm + mf * 16, kk, lane));
        }
        uint32_t bh[4][2], bl[4][2];
#pragma unroll
        for (int np = 0; np < 2; np++) {
            uint32_t t[4];
            ldm_x4(t, b_addrT<LDW_>(sWh, wn + np * 16, kk, lane));
            bh[np * 2][0] = t[0]; bh[np * 2][1] = t[1];
            bh[np * 2 + 1][0] = t[2]; bh[np * 2 + 1][1] = t[3];
            ldm_x4(t, b_addrT<LDW_>(sWl, wn + np * 16, kk, lane));
            bl[np * 2][0] = t[0]; bl[np * 2][1] = t[1];
            bl[np * 2 + 1][0] = t[2]; bl[np * 2 + 1][1] = t[3];
        }
#pragma unroll
        for (int mf = 0; mf < 2; mf++)
#pragma unroll
            for (int nf = 0; nf < 4; nf++) {
                mma_bf(acc[mf][nf], ah[mf], bh[nf]);
                mma_bf(acc[mf][nf], ah[mf], bl[nf]);
                mma_bf(acc[mf][nf], al[mf], bh[nf]);
            }
    }

    const int qr = lane >> 2, qc = (lane & 3) * 2;
    float* P = g_part + (size_t)ks * BATCH * G4 + (size_t)wm * G4 + bn * 128 + wn;
#pragma unroll
    for (int mf = 0; mf < 2; mf++)
#pragma unroll
        for (int nf = 0; nf < 4; nf++) {
            float* p = P + (size_t)(mf * 16 + qr) * G4 + nf * 8 + qc;
            *(float2*)p = make_float2(acc[mf][nf][0], acc[mf][nf][1]);
            *(float2*)(p + (size_t)8 * G4) = make_float2(acc[mf][nf][2], acc[mf][nf][3]);
        }
}

// ---------------------------------------------------------------------------
// Pointwise / LayerNorm (device fn). One block per batch row b (bid < 64).
// g_part re-read at identical addresses cross-block every step -> __ldcg.
// ---------------------------------------------------------------------------
__device__ __forceinline__ void blk_stats(float v0, float v1, float v2, float v3,
                                          float* sred, float& mean, float& rstd) {
    float s1 = v0 + v1 + v2 + v3;
    float s2 = v0 * v0 + v1 * v1 + v2 * v2 + v3 * v3;
#pragma unroll
    for (int o = 16; o > 0; o >>= 1) {
        s1 += __shfl_xor_sync(0xffffffffu, s1, o);
        s2 += __shfl_xor_sync(0xffffffffu, s2, o);
    }
    const int w = threadIdx.x >> 5;
    if ((threadIdx.x & 31) == 0) { sred[w] = s1; sred[8 + w] = s2; }
    __syncthreads();
    s1 = sred[0] + sred[1] + sred[2] + sred[3] + sred[4] + sred[5] + sred[6] + sred[7];
    s2 = sred[8] + sred[9] + sred[10] + sred[11] + sred[12] + sred[13] + sred[14] + sred[15];
    __syncthreads();
    mean = s1 * (1.f / 1024.f);
    float var = s2 * (1.f / 1024.f) - mean * mean;
    rstd = rsqrtf(var + 1e-5f);
}

__device__ __forceinline__ float sigm(float x) { return 1.f / (1.f + expf(-x)); }

__device__ __forceinline__ void step_point_dev(
    int t, int b, int tid, const float* __restrict__ cell0,
    const float* __restrict__ wch, const float* __restrict__ bias,
    const float* __restrict__ gf, const float* __restrict__ gi,
    const float* __restrict__ gg, const float* __restrict__ go,
    const float* __restrict__ gcell, const float* __restrict__ bcell,
    float* __restrict__ out, float* sred) {
    const float* xp = g_xproj + ((size_t)t * BATCH + b) * G4;
    const float* p = g_part + (size_t)b * G4;
    const size_t PS = (size_t)BATCH * G4;

    float vf[4], vi[4], vg[4], vo[4], cold[4];
    int hh[4];
#pragma unroll
    for (int j = 0; j < 4; j++) {
        const int h = tid + j * 256;
        hh[j] = h;
        cold[j] = (t == 0) ? cell0[b * H_DIM + h] : g_c[b * H_DIM + h];
#pragma unroll
        for (int g = 0; g < 4; g++) {
            float s = xp[g * H_DIM + h];
            s += __ldcg(p + 0 * PS + g * H_DIM + h);
            s += __ldcg(p + 1 * PS + g * H_DIM + h);
            s += __ldcg(p + 2 * PS + g * H_DIM + h);
            s += __ldcg(p + 3 * PS + g * H_DIM + h);
            if (g == 0) vf[j] = s + wch[h] * cold[j];
            else if (g == 1) vi[j] = s + wch[H_DIM + h] * cold[j];
            else if (g == 2) vg[j] = s;
            else vo[j] = s;
        }
    }

    float mf, rf, mi, ri, mg, rg;
    blk_stats(vf[0], vf[1], vf[2], vf[3], sred, mf, rf);
    blk_stats(vi[0], vi[1], vi[2], vi[3], sred, mi, ri);
    blk_stats(vg[0], vg[1], vg[2], vg[3], sred, mg, rg);

    float cn[4];
#pragma unroll
    for (int j = 0; j < 4; j++) {
        const int h = hh[j];
        const float fj = sigm((vf[j] - mf) * rf * gf[h] + bias[h]);
        const float ij = sigm((vi[j] - mi) * ri * gi[h] + bias[H_DIM + h]);
        const float gj = tanhf((vg[j] - mg) * rg * gg[h] + bias[2 * H_DIM + h]);
        cn[j] = fj * cold[j] + ij * gj;
    }

    float mc, rc;
    blk_stats(cn[0], cn[1], cn[2], cn[3], sred, mc, rc);

#pragma unroll
    for (int j = 0; j < 4; j++)
        vo[j] += wch[2 * H_DIM + hh[j]] * cn[j];

    float mo, ro;
    blk_stats(vo[0], vo[1], vo[2], vo[3], sred, mo, ro);

#pragma unroll
    for (int j = 0; j < 4; j++) {
        const int h = hh[j];
        const float oj = sigm((vo[j] - mo) * ro * go[h] + bias[3 * H_DIM + h]);
        const float cln = (cn[j] - mc) * rc * gcell[h] + bcell[h];
        const float hn = oj * tanhf(cln);
        out[((size_t)t * BATCH + b) * H_DIM + h] = hn;
        g_c[b * H_DIM + h] = cn[j];
    }
}

// ---------------------------------------------------------------------------
// Persistent recurrence kernel. Dynamic smem layout (bf16 elems):
//   [0, 33792)        Wh   128 x LDW_
//   [33792, 67584)    Wl
//   [67584, 84480)    Ah    64 x LDW_
//   [84480, 101376)   Al            -> 202752 bytes total
// ---------------------------------------------------------------------------
#define SMEM_DYN_BYTES (2 * (128 * LDW_ + 64 * LDW_) * 2)

__global__ __launch_bounds__(256) void recur_persist(
    const float* __restrict__ hidden, const float* __restrict__ cell0,
    const float* __restrict__ Whh, const float* __restrict__ wch,
    const float* __restrict__ bias,
    const float* __restrict__ gf, const float* __restrict__ gi,
    const float* __restrict__ gg, const float* __restrict__ go,
    const float* __restrict__ gcell, const float* __restrict__ bcell,
    float* __restrict__ out) {
    extern __shared__ __nv_bfloat16 dsm[];
    __nv_bfloat16* Wh = dsm;
    __nv_bfloat16* Wl = dsm + 128 * LDW_;
    __nv_bfloat16* Ah = dsm + 2 * 128 * LDW_;
    __nv_bfloat16* Al = dsm + 2 * 128 * LDW_ + 64 * LDW_;
    __shared__ float sred[16];

    const int bid = blockIdx.x;
    const int tid = threadIdx.x;
    const int bn = bid & 31;            // N tile (128 wide)
    const int ks = bid >> 5;            // K chunk (256 wide)

    // Prologue: convert this block's W chunk (128 x 256 fp32) to resident
    // split-bf16 smem, once for all 512 steps.
    {
        const float* Wb = Whh + (size_t)(bn * 128) * H_DIM + ks * 256;
#pragma unroll
        for (int i = 0; i < 32; i++) {
            int idx = tid + i * 256;        // 0..8191 float4 slots
            int n = idx >> 6, c4 = (idx & 63) * 4;
            float4 v = *(const float4*)(Wb + (size_t)n * H_DIM + c4);
            split_store4(v, &Wh[n * LDW_ + c4], &Wl[n * LDW_ + c4]);
        }
        __syncthreads();
    }

    for (int t = 0; t < T_STEPS; t++) {
        const float* h = (t == 0) ? hidden : out + (size_t)(t - 1) * BATCH * H_DIM;
        step_gemm_res(h, bn, ks, tid, Ah, Al, Wh, Wl);
        grid_bar(2 * t);
        if (bid < BATCH)
            step_point_dev(t, bid, tid, cell0, wch, bias, gf, gi, gg, go, gcell, bcell, out, sred);
        grid_bar(2 * t + 1);
    }

    // Finalize: h_f = out[T-1], c_f = g_c (appended after out).
    const size_t base = (size_t)T_STEPS * BATCH * H_DIM;
    for (int i = bid * 256 + tid; i < BATCH * H_DIM; i += NBLK * 256) {
        out[base + i] = out[(size_t)(T_STEPS - 1) * BATCH * H_DIM + i];
        out[base + (size_t)BATCH * H_DIM + i] = __ldcg(&g_c[i]);
    }
}

// ---------------------------------------------------------------------------
extern "C" void kernel_launch(void* const* d_in, const int* in_sizes, int n_in,
                              void* d_out, int out_size) {
    const float* input  = (const float*)d_in[0];
    const float* hidden = (const float*)d_in[1];
    const float* cell   = (const float*)d_in[2];
    const float* wih    = (const float*)d_in[3];
    const float* whh    = (const float*)d_in[4];
    const float* wch    = (const float*)d_in[5];
    const float* bias   = (const float*)d_in[6];
    const float* gf     = (const float*)d_in[7];
    const float* gi     = (const float*)d_in[8];
    const float* gg     = (const float*)d_in[9];
    const float* go     = (const float*)d_in[10];
    const float* gcell  = (const float*)d_in[11];
    const float* bcell  = (const float*)d_in[12];
    float* out = (float*)d_out;

    cudaFuncSetAttribute(recur_persist,
                         cudaFuncAttributeMaxDynamicSharedMemorySize,
                         SMEM_DYN_BYTES);

    // 3-node graph: barrier reset, x_proj GEMM, persistent recurrence.
    zero_bar_k<<<64, 256>>>();
    xproj_gemm<<<dim3(G4 / 128, (T_STEPS * BATCH) / 128), 256>>>(input, wih);
    recur_persist<<<NBLK, 256, SMEM_DYN_BYTES>>>(hidden, cell, whh, wch, bias,
                                                 gf, gi, gg, go, gcell, bcell, out);
}

// round 11
// speedup vs baseline: 2.6260x; 1.0996x over previous
#include <cuda_runtime.h>
#include <cuda_bf16.h>
#include <stdint.h>
#include <math.h>

// ---------------------------------------------------------------------------
// Problem constants
// ---------------------------------------------------------------------------
#define T_STEPS 512
#define BATCH   64
#define IN_DIM  1024
#define H_DIM   1024
#define G4      4096            // 4*H
#define KSPLIT  4               // split-K for the per-step GEMM
#define NBLK    128             // persistent-kernel grid (1 blk/SM, <=148 SMs)
#define NBAR    (2 * T_STEPS)   // grid barriers used per launch
#define LDS_    40              // xproj smem leading dim (bf16)
#define LDW_    264             // resident-W / A smem leading dim (bf16); 528B rows

// Scratch (static __device__ arrays: allocation-free per harness rules)
__device__ float g_xproj[(size_t)T_STEPS * BATCH * G4];   // input projection
__device__ float g_part[KSPLIT * BATCH * G4];             // split-K partials
__device__ float g_c[BATCH * H_DIM];                      // cell state
__device__ int   g_cnt[NBAR];                             // barrier arrival counters
__device__ int   g_flag[NBAR];                            // barrier release flags

// ---------------------------------------------------------------------------
// Grid barrier v3: single arrival counter + release flag. Arrival atomics are
// hidden by inter-block skew; release is one flag store + single-address polls.
// ---------------------------------------------------------------------------
__device__ __forceinline__ void grid_bar(int slot) {
    __syncthreads();
    if (threadIdx.x == 0) {
        __threadfence();                         // release this block's stores
        int old = atomicAdd(&g_cnt[slot], 1);
        if (old == NBLK - 1) {
            *((volatile int*)&g_flag[slot]) = 1; // last arriver releases all
        } else {
            while (*((volatile int*)&g_flag[slot]) == 0) __nanosleep(32);
        }
        __threadfence();                         // acquire other blocks' stores
    }
    __syncthreads();
}

__global__ void zero_bar_k() {
    int i = blockIdx.x * 256 + threadIdx.x;
    if (i < NBAR) { g_cnt[i] = 0; g_flag[i] = 0; }
}

// ---------------------------------------------------------------------------
// Tensor-core helpers: mma.sync m16n8k16 bf16 + ldmatrix
// ---------------------------------------------------------------------------
__device__ __forceinline__ uint32_t smem_u32(const void* p) {
    return (uint32_t)__cvta_generic_to_shared(p);
}

__device__ __forceinline__ void ldm_x4(uint32_t r[4], uint32_t a) {
    asm volatile("ldmatrix.sync.aligned.m8n8.x4.shared.b16 {%0,%1,%2,%3}, [%4];\n"
                 : "=r"(r[0]), "=r"(r[1]), "=r"(r[2]), "=r"(r[3]) : "r"(a));
}

__device__ __forceinline__ void mma_bf(float d[4], const uint32_t a[4], const uint32_t b[2]) {
    asm volatile(
        "mma.sync.aligned.m16n8k16.row.col.f32.bf16.bf16.f32 "
        "{%0,%1,%2,%3}, {%4,%5,%6,%7}, {%8,%9}, {%0,%1,%2,%3};\n"
        : "+f"(d[0]), "+f"(d[1]), "+f"(d[2]), "+f"(d[3])
        : "r"(a[0]), "r"(a[1]), "r"(a[2]), "r"(a[3]), "r"(b[0]), "r"(b[1]));
}

template <int LD>
__device__ __forceinline__ uint32_t a_addrT(uint32_t base, int m0, int k0, int lane) {
    int r = m0 + (lane & 7) + ((lane >> 3) & 1) * 8;
    int c = k0 + (lane >> 4) * 8;
    return base + (uint32_t)(r * LD + c) * 2u;
}
template <int LD>
__device__ __forceinline__ uint32_t b_addrT(uint32_t base, int n0, int k0, int lane) {
    int r = n0 + (lane & 7) + ((lane >> 4) & 1) * 8;
    int c = k0 + ((lane >> 3) & 1) * 8;
    return base + (uint32_t)(r * LD + c) * 2u;
}

// Split fp32x4 -> bf16 hi/lo x4, store to smem (4B-aligned positions)
__device__ __forceinline__ void split_store4(float4 v, __nv_bfloat16* hi, __nv_bfloat16* lo) {
    __nv_bfloat16 h0 = __float2bfloat16(v.x), h1 = __float2bfloat16(v.y);
    __nv_bfloat16 h2 = __float2bfloat16(v.z), h3 = __float2bfloat16(v.w);
    __nv_bfloat16 l0 = __float2bfloat16(v.x - __bfloat162float(h0));
    __nv_bfloat16 l1 = __float2bfloat16(v.y - __bfloat162float(h1));
    __nv_bfloat16 l2 = __float2bfloat16(v.z - __bfloat162float(h2));
    __nv_bfloat16 l3 = __float2bfloat16(v.w - __bfloat162float(h3));
    uint32_t* hp = (uint32_t*)hi;
    uint32_t* lp = (uint32_t*)lo;
    __nv_bfloat162 t0 = __halves2bfloat162(h0, h1);
    __nv_bfloat162 t1 = __halves2bfloat162(h2, h3);
    __nv_bfloat162 t2 = __halves2bfloat162(l0, l1);
    __nv_bfloat162 t3 = __halves2bfloat162(l2, l3);
    hp[0] = *(uint32_t*)&t0;
    hp[1] = *(uint32_t*)&t1;
    lp[0] = *(uint32_t*)&t2;
    lp[1] = *(uint32_t*)&t3;
}

// ---------------------------------------------------------------------------
// Kernel: x_proj = input @ weight_ih^T   (split-bf16 tensor cores) — unchanged
// ---------------------------------------------------------------------------
__global__ __launch_bounds__(256) void xproj_gemm(const float* __restrict__ A,
                                                  const float* __restrict__ W) {
    __shared__ __align__(16) __nv_bfloat16 Ah[128 * LDS_], Al[128 * LDS_];
    __shared__ __align__(16) __nv_bfloat16 Bh[128 * LDS_], Bl[128 * LDS_];

    const int bn = blockIdx.x, bm = blockIdx.y, tid = threadIdx.x;
    const int wid = tid >> 5, lane = tid & 31;
    const int wm = (wid >> 1) * 32;
    const int wn = (wid & 1) * 64;

    float acc[2][8][4];
#pragma unroll
    for (int i = 0; i < 2; i++)
#pragma unroll
        for (int j = 0; j < 8; j++)
#pragma unroll
            for (int k = 0; k < 4; k++) acc[i][j][k] = 0.f;

    const float* Ab = A + (size_t)bm * 128 * IN_DIM;
    const float* Wb = W + (size_t)bn * 128 * IN_DIM;
    const int lr = tid >> 3;
    const int lc = (tid & 7) * 4;

    const uint32_t sAh = smem_u32(Ah), sAl = smem_u32(Al);
    const uint32_t sBh = smem_u32(Bh), sBl = smem_u32(Bl);

    float4 av[4], wv[4];
#pragma unroll
    for (int i = 0; i < 4; i++) {
        av[i] = *(const float4*)(Ab + (size_t)(lr + i * 32) * IN_DIM + lc);
        wv[i] = *(const float4*)(Wb + (size_t)(lr + i * 32) * IN_DIM + lc);
    }

    for (int kt = 0; kt < IN_DIM; kt += 32) {
#pragma unroll
        for (int i = 0; i < 4; i++) {
            int r = lr + i * 32;
            split_store4(av[i], &Ah[r * LDS_ + lc], &Al[r * LDS_ + lc]);
            split_store4(wv[i], &Bh[r * LDS_ + lc], &Bl[r * LDS_ + lc]);
        }
        __syncthreads();
        if (kt + 32 < IN_DIM) {
#pragma unroll
            for (int i = 0; i < 4; i++) {
                av[i] = *(const float4*)(Ab + (size_t)(lr + i * 32) * IN_DIM + kt + 32 + lc);
                wv[i] = *(const float4*)(Wb + (size_t)(lr + i * 32) * IN_DIM + kt + 32 + lc);
            }
        }
#pragma unroll
        for (int kk = 0; kk < 32; kk += 16) {
            uint32_t ah[2][4], al[2][4];
#pragma unroll
            for (int mf = 0; mf < 2; mf++) {
                ldm_x4(ah[mf], a_addrT<LDS_>(sAh, wm + mf * 16, kk, lane));
                ldm_x4(al[mf], a_addrT<LDS_>(sAl, wm + mf * 16, kk, lane));
            }
            uint32_t bh[8][2], bl[8][2];
#pragma unroll
            for (int np = 0; np < 4; np++) {
                uint32_t t[4];
                ldm_x4(t, b_addrT<LDS_>(sBh, wn + np * 16, kk, lane));
                bh[np * 2][0] = t[0]; bh[np * 2][1] = t[1];
                bh[np * 2 + 1][0] = t[2]; bh[np * 2 + 1][1] = t[3];
                ldm_x4(t, b_addrT<LDS_>(sBl, wn + np * 16, kk, lane));
                bl[np * 2][0] = t[0]; bl[np * 2][1] = t[1];
                bl[np * 2 + 1][0] = t[2]; bl[np * 2 + 1][1] = t[3];
            }
#pragma unroll
            for (int mf = 0; mf < 2; mf++)
#pragma unroll
                for (int nf = 0; nf < 8; nf++) {
                    mma_bf(acc[mf][nf], ah[mf], bh[nf]);
                    mma_bf(acc[mf][nf], ah[mf], bl[nf]);
                    mma_bf(acc[mf][nf], al[mf], bh[nf]);
                }
        }
        __syncthreads();
    }

    const int qr = lane >> 2, qc = (lane & 3) * 2;
    float* Cb = g_xproj + ((size_t)(bm * 128 + wm)) * G4 + bn * 128 + wn;
#pragma unroll
    for (int mf = 0; mf < 2; mf++)
#pragma unroll
        for (int nf = 0; nf < 8; nf++) {
            float* p = Cb + (size_t)(mf * 16 + qr) * G4 + nf * 8 + qc;
            *(float2*)p = make_float2(acc[mf][nf][0], acc[mf][nf][1]);
            *(float2*)(p + (size_t)8 * G4) = make_float2(acc[mf][nf][2], acc[mf][nf][3]);
        }
}

// ---------------------------------------------------------------------------
// Per-step GEMM with RESIDENT split-bf16 W in smem (unchanged from R9).
// ---------------------------------------------------------------------------
__device__ __forceinline__ void step_gemm_res(
    const float* __restrict__ h, int bn, int ks, int tid,
    __nv_bfloat16* Ah, __nv_bfloat16* Al,
    const __nv_bfloat16* Wh, const __nv_bfloat16* Wl) {
    const int k0 = ks * 256;

#pragma unroll
    for (int i = 0; i < 16; i++) {
        int idx = tid + i * 256;
        int n = idx >> 6, c4 = (idx & 63) * 4;
        float4 v = *(const float4*)(h + (size_t)n * H_DIM + k0 + c4);
        split_store4(v, &Ah[n * LDW_ + c4], &Al[n * LDW_ + c4]);
    }
    __syncthreads();

    const int wid = tid >> 5, lane = tid & 31;
    const int wm = (wid >> 2) * 32;
    const int wn = (wid & 3) * 32;

    float acc[2][4][4];
#pragma unroll
    for (int i = 0; i < 2; i++)
#pragma unroll
        for (int j = 0; j < 4; j++)
#pragma unroll
            for (int k = 0; k < 4; k++) acc[i][j][k] = 0.f;

    const uint32_t sAh = smem_u32(Ah), sAl = smem_u32(Al);
    const uint32_t sWh = smem_u32(Wh), sWl = smem_u32(Wl);

#pragma unroll 4
    for (int kk = 0; kk < 256; kk += 16) {
        uint32_t ah[2][4], al[2][4];
#pragma unroll
        for (int mf = 0; mf < 2; mf++) {
            ldm_x4(ah[mf], a_addrT<LDW_>(sAh, wm + mf * 16, kk, lane));
            ldm_x4(al[mf], a_addrT<LDW_>(sAl, wm + mf * 16, kk, lane));
        }
        uint32_t bh[4][2], bl[4][2];
#pragma unroll
        for (int np = 0; np < 2; np++) {
            uint32_t t[4];
            ldm_x4(t, b_addrT<LDW_>(sWh, wn + np * 16, kk, lane));
            bh[np * 2][0] = t[0]; bh[np * 2][1] = t[1];
            bh[np * 2 + 1][0] = t[2]; bh[np * 2 + 1][1] = t[3];
            ldm_x4(t, b_addrT<LDW_>(sWl, wn + np * 16, kk, lane));
            bl[np * 2][0] = t[0]; bl[np * 2][1] = t[1];
            bl[np * 2 + 1][0] = t[2]; bl[np * 2 + 1][1] = t[3];
        }
#pragma unroll
        for (int mf = 0; mf < 2; mf++)
#pragma unroll
            for (int nf = 0; nf < 4; nf++) {
                mma_bf(acc[mf][nf], ah[mf], bh[nf]);
                mma_bf(acc[mf][nf], ah[mf], bl[nf]);
                mma_bf(acc[mf][nf], al[mf], bh[nf]);
            }
    }

    const int qr = lane >> 2, qc = (lane & 3) * 2;
    float* P = g_part + (size_t)ks * BATCH * G4 + (size_t)wm * G4 + bn * 128 + wn;
#pragma unroll
    for (int mf = 0; mf < 2; mf++)
#pragma unroll
        for (int nf = 0; nf < 4; nf++) {
            float* p = P + (size_t)(mf * 16 + qr) * G4 + nf * 8 + qc;
            *(float2*)p = make_float2(acc[mf][nf][0], acc[mf][nf][1]);
            *(float2*)(p + (size_t)8 * G4) = make_float2(acc[mf][nf][2], acc[mf][nf][3]);
        }
}

// ---------------------------------------------------------------------------
// Pointwise / LayerNorm (vectorized). One block per batch row b (bid < 64).
// Each thread owns 4 CONTIGUOUS channels h = tid*4 .. tid*4+3 -> float4 I/O.
// Reductions merged: round 1 = f/i/g stats (6 values), round 2 = c/o (4).
// ---------------------------------------------------------------------------
template <int N>
__device__ __forceinline__ void multi_red(float* v, float* sred) {
#pragma unroll
    for (int o = 16; o > 0; o >>= 1)
#pragma unroll
        for (int k = 0; k < N; k++) v[k] += __shfl_xor_sync(0xffffffffu, v[k], o);
    const int w = threadIdx.x >> 5;
    if ((threadIdx.x & 31) == 0)
#pragma unroll
        for (int k = 0; k < N; k++) sred[w * N + k] = v[k];
    __syncthreads();
#pragma unroll
    for (int k = 0; k < N; k++) {
        float s = 0.f;
#pragma unroll
        for (int w8 = 0; w8 < 8; w8++) s += sred[w8 * N + k];
        v[k] = s;
    }
    __syncthreads();
}

__device__ __forceinline__ float sigm(float x) { return 1.f / (1.f + expf(-x)); }

__device__ __forceinline__ void step_point_dev(
    int t, int b, int tid, const float* __restrict__ cell0,
    const float* __restrict__ wch, const float* __restrict__ bias,
    const float* __restrict__ gf, const float* __restrict__ gi,
    const float* __restrict__ gg, const float* __restrict__ go,
    const float* __restrict__ gcell, const float* __restrict__ bcell,
    float* __restrict__ out, float* sred) {
    const float4* xp4 = (const float4*)(g_xproj + ((size_t)t * BATCH + b) * G4);
    const float4* p4  = (const float4*)(g_part + (size_t)b * G4);
    const int PS4 = BATCH * G4 / 4;     // float4 stride between split-K partials

    // Gather gates: 4 x (1 xproj + 4 partial) float4 loads
    float vf[4], vi[4], vg[4], vo[4];
#pragma unroll
    for (int g = 0; g < 4; g++) {
        float4 s = xp4[g * 256 + tid];
#pragma unroll
        for (int k = 0; k < KSPLIT; k++) {
            float4 q = __ldcg(&p4[k * PS4 + g * 256 + tid]);
            s.x += q.x; s.y += q.y; s.z += q.z; s.w += q.w;
        }
        float* dst = (g == 0) ? vf : (g == 1) ? vi : (g == 2) ? vg : vo;
        dst[0] = s.x; dst[1] = s.y; dst[2] = s.z; dst[3] = s.w;
    }

    const float4* wch4 = (const float4*)wch;
    float4 wcf = wch4[tid], wci = wch4[256 + tid], wco = wch4[512 + tid];
    float4 cold4 = (t == 0) ? ((const float4*)cell0)[b * 256 + tid]
                            : ((float4*)g_c)[b * 256 + tid];
    float cold[4] = {cold4.x, cold4.y, cold4.z, cold4.w};
    const float wcf_[4] = {wcf.x, wcf.y, wcf.z, wcf.w};
    const float wci_[4] = {wci.x, wci.y, wci.z, wci.w};
    const float wco_[4] = {wco.x, wco.y, wco.z, wco.w};

#pragma unroll
    for (int j = 0; j < 4; j++) {
        vf[j] += wcf_[j] * cold[j];
        vi[j] += wci_[j] * cold[j];
    }

    // Round 1: f/i/g stats together
    float r1[6] = {0.f, 0.f, 0.f, 0.f, 0.f, 0.f};
#pragma unroll
    for (int j = 0; j < 4; j++) {
        r1[0] += vf[j]; r1[1] += vf[j] * vf[j];
        r1[2] += vi[j]; r1[3] += vi[j] * vi[j];
        r1[4] += vg[j]; r1[5] += vg[j] * vg[j];
    }
    multi_red<6>(r1, sred);
    const float inv = 1.f / 1024.f;
    float mf = r1[0] * inv, rf = rsqrtf(r1[1] * inv - mf * mf + 1e-5f);
    float mi = r1[2] * inv, ri = rsqrtf(r1[3] * inv - mi * mi + 1e-5f);
    float mg = r1[4] * inv, rg = rsqrtf(r1[5] * inv - mg * mg + 1e-5f);

    // Per-channel params (float4)
    float4 gf4 = ((const float4*)gf)[tid], gi4 = ((const float4*)gi)[tid];
    float4 gg4 = ((const float4*)gg)[tid], go4 = ((const float4*)go)[tid];
    float4 bf4 = ((const float4*)bias)[tid];
    float4 bi4 = ((const float4*)bias)[256 + tid];
    float4 bg4 = ((const float4*)bias)[512 + tid];
    float4 bo4 = ((const float4*)bias)[768 + tid];
    const float gf_[4] = {gf4.x, gf4.y, gf4.z, gf4.w};
    const float gi_[4] = {gi4.x, gi4.y, gi4.z, gi4.w};
    const float gg_[4] = {gg4.x, gg4.y, gg4.z, gg4.w};
    const float go_[4] = {go4.x, go4.y, go4.z, go4.w};
    const float bf_[4] = {bf4.x, bf4.y, bf4.z, bf4.w};
    const float bi_[4] = {bi4.x, bi4.y, bi4.z, bi4.w};
    const float bg_[4] = {bg4.x, bg4.y, bg4.z, bg4.w};
    const float bo_[4] = {bo4.x, bo4.y, bo4.z, bo4.w};

    float cn[4];
#pragma unroll
    for (int j = 0; j < 4; j++) {
        const float fj = sigm((vf[j] - mf) * rf * gf_[j] + bf_[j]);
        const float ij = sigm((vi[j] - mi) * ri * gi_[j] + bi_[j]);
        const float gj = tanhf((vg[j] - mg) * rg * gg_[j] + bg_[j]);
        cn[j] = fj * cold[j] + ij * gj;
        vo[j] += wco_[j] * cn[j];
    }

    // Round 2: c and o stats together
    float r2[4] = {0.f, 0.f, 0.f, 0.f};
#pragma unroll
    for (int j = 0; j < 4; j++) {
        r2[0] += cn[j]; r2[1] += cn[j] * cn[j];
        r2[2] += vo[j]; r2[3] += vo[j] * vo[j];
    }
    multi_red<4>(r2, sred);
    float mc = r2[0] * inv, rc = rsqrtf(r2[1] * inv - mc * mc + 1e-5f);
    float mo = r2[2] * inv, ro = rsqrtf(r2[3] * inv - mo * mo + 1e-5f);

    float4 gc4v = ((const float4*)gcell)[tid];
    float4 bc4v = ((const float4*)bcell)[tid];
    const float gc_[4] = {gc4v.x, gc4v.y, gc4v.z, gc4v.w};
    const float bc_[4] = {bc4v.x, bc4v.y, bc4v.z, bc4v.w};

    float hn[4];
#pragma unroll
    for (int j = 0; j < 4; j++) {
        const float oj = sigm((vo[j] - mo) * ro * go_[j] + bo_[j]);
        const float cln = (cn[j] - mc) * rc * gc_[j] + bc_[j];
        hn[j] = oj * tanhf(cln);
    }

    ((float4*)out)[((size_t)t * BATCH + b) * 256 + tid] =
        make_float4(hn[0], hn[1], hn[2], hn[3]);
    ((float4*)g_c)[b * 256 + tid] = make_float4(cn[0], cn[1], cn[2], cn[3]);
}

// ---------------------------------------------------------------------------
// Persistent recurrence kernel. Dynamic smem: Wh|Wl (128 x LDW_) + Ah|Al (64 x LDW_)
// ---------------------------------------------------------------------------
#define SMEM_DYN_BYTES (2 * (128 * LDW_ + 64 * LDW_) * 2)

__global__ __launch_bounds__(256) void recur_persist(
    const float* __restrict__ hidden, const float* __restrict__ cell0,
    const float* __restrict__ Whh, const float* __restrict__ wch,
    const float* __restrict__ bias,
    const float* __restrict__ gf, const float* __restrict__ gi,
    const float* __restrict__ gg, const float* __restrict__ go,
    const float* __restrict__ gcell, const float* __restrict__ bcell,
    float* __restrict__ out) {
    extern __shared__ __nv_bfloat16 dsm[];
    __nv_bfloat16* Wh = dsm;
    __nv_bfloat16* Wl = dsm + 128 * LDW_;
    __nv_bfloat16* Ah = dsm + 2 * 128 * LDW_;
    __nv_bfloat16* Al = dsm + 2 * 128 * LDW_ + 64 * LDW_;
    __shared__ float sred[48];

    const int bid = blockIdx.x;
    const int tid = threadIdx.x;
    const int bn = bid & 31;            // N tile (128 wide)
    const int ks = bid >> 5;            // K chunk (256 wide)

    // Prologue: convert this block's W chunk (128 x 256 fp32) once.
    {
        const float* Wb = Whh + (size_t)(bn * 128) * H_DIM + ks * 256;
#pragma unroll
        for (int i = 0; i < 32; i++) {
            int idx = tid + i * 256;
            int n = idx >> 6, c4 = (idx & 63) * 4;
            float4 v = *(const float4*)(Wb + (size_t)n * H_DIM + c4);
            split_store4(v, &Wh[n * LDW_ + c4], &Wl[n * LDW_ + c4]);
        }
        __syncthreads();
    }

    for (int t = 0; t < T_STEPS; t++) {
        const float* h = (t == 0) ? hidden : out + (size_t)(t - 1) * BATCH * H_DIM;
        step_gemm_res(h, bn, ks, tid, Ah, Al, Wh, Wl);
        grid_bar(2 * t);
        if (bid < BATCH)
            step_point_dev(t, bid, tid, cell0, wch, bias, gf, gi, gg, go, gcell, bcell, out, sred);
        grid_bar(2 * t + 1);
    }

    // Finalize: h_f = out[T-1], c_f = g_c (appended after out), float4.
    const size_t base4 = (size_t)T_STEPS * BATCH * H_DIM / 4;
    float4* out4 = (float4*)out;
    const int tot4 = BATCH * H_DIM / 4;
    for (int i = bid * 256 + tid; i < tot4; i += NBLK * 256) {
        out4[base4 + i] = out4[(size_t)(T_STEPS - 1) * BATCH * H_DIM / 4 + i];
        out4[base4 + tot4 + i] = __ldcg(&((float4*)g_c)[i]);
    }
}

// ---------------------------------------------------------------------------
extern "C" void kernel_launch(void* const* d_in, const int* in_sizes, int n_in,
                              void* d_out, int out_size) {
    const float* input  = (const float*)d_in[0];
    const float* hidden = (const float*)d_in[1];
    const float* cell   = (const float*)d_in[2];
    const float* wih    = (const float*)d_in[3];
    const float* whh    = (const float*)d_in[4];
    const float* wch    = (const float*)d_in[5];
    const float* bias   = (const float*)d_in[6];
    const float* gf     = (const float*)d_in[7];
    const float* gi     = (const float*)d_in[8];
    const float* gg     = (const float*)d_in[9];
    const float* go     = (const float*)d_in[10];
    const float* gcell  = (const float*)d_in[11];
    const float* bcell  = (const float*)d_in[12];
    float* out = (float*)d_out;

    cudaFuncSetAttribute(recur_persist,
                         cudaFuncAttributeMaxDynamicSharedMemorySize,
                         SMEM_DYN_BYTES);

    // 3-node graph: barrier reset, x_proj GEMM, persistent recurrence.
    zero_bar_k<<<(NBAR + 255) / 256, 256>>>();
    xproj_gemm<<<dim3(G4 / 128, (T_STEPS * BATCH) / 128), 256>>>(input, wih);
    recur_persist<<<NBLK, 256, SMEM_DYN_BYTES>>>(hidden, cell, whh, wch, bias,
                                                 gf, gi, gg, go, gcell, bcell, out);
}